// round 2
// baseline (speedup 1.0000x reference)
#include <cuda_runtime.h>

// ---------------- problem constants ----------------
#define GRID     128      // CTAs (<= #SMs, all co-resident -> global barrier safe)
#define NTHREADS 256
#define SQ       2048     // sequence length
#define BATCH    64
#define H        512
#define HB       (H*BATCH)   // 32768 floats per h snapshot
#define RPC      16          // gate rows per CTA (= 4 units x 4 gates)
#define GPLD     68          // padded ld for gate-partial smem tile

// ---------------- device scratch (static: no allocation allowed) ----------------
__device__ __align__(16) float g_h1[(SQ + 1) * HB];   // layer-1 h history (slot 0 = zeros)
__device__ __align__(16) float g_h2[2 * HB];          // layer-2 h double buffer
__device__ __align__(16) float g_E2[16 * 4 * H];      // E2[p][r]: (embed[i]+embed[j]) @ Wih1^T
__device__ int      g_pidx[SQ * BATCH];    // pair index per (s,b)
__device__ unsigned g_isI32;               // inp dtype flag (1 = int32, 0 = int64)
__device__ unsigned g_barcnt;
__device__ unsigned g_bargen;

__device__ __forceinline__ float sigmoidf_(float x) { return 1.f / (1.f + expf(-x)); }

// Sense-reversing centralized grid barrier (replay-safe: count returns to 0,
// generation is monotonic across graph replays).
__device__ __forceinline__ void grid_barrier() {
    __syncthreads();
    if (threadIdx.x == 0) {
        __threadfence();
        unsigned g = *((volatile unsigned*)&g_bargen);
        if (atomicAdd(&g_barcnt, 1u) == GRID - 1u) {
            atomicExch(&g_barcnt, 0u);
            __threadfence();
            atomicExch(&g_bargen, g + 1u);
        } else {
            while (*((volatile unsigned*)&g_bargen) == g) { }
        }
        __threadfence();
    }
    __syncthreads();
}

// ---------------- setup kernels ----------------
// dtype probe: view first SQ*BATCH u32 words (safe under BOTH dtypes).
// int64 data with values in [0,4) -> every odd word is 0.
// int32 data -> odd words are values in [0,4); some of 131072 are nonzero.
__global__ void detect_reset() { g_isI32 = 0u; }

__global__ void detect_dtype(const unsigned* __restrict__ w) {
    int i = blockIdx.x * blockDim.x + threadIdx.x;   // 512*256 = 131072 probes
    if (i < (SQ * BATCH) / 2 * 1 + (SQ * BATCH) / 2 - (SQ * BATCH) / 2) {} // no-op
    if (i < (SQ * BATCH)) {
        // probe odd words of the first SQ*BATCH words (1 MB)
        if ((i & 1) && w[i] != 0u) atomicOr(&g_isI32, 1u);
    }
}

__global__ void setup_misc(const void* __restrict__ inp_raw) {
    int i = blockIdx.x * blockDim.x + threadIdx.x;    // 512*256 = SQ*BATCH
    if (i < SQ * BATCH) {
        int s = i >> 6, b = i & 63;
        long long a, c;
        if (g_isI32) {
            const int* p = (const int*)inp_raw;
            a = p[b * SQ + s];
            c = p[(BATCH + b) * SQ + s];
        } else {
            const long long* p = (const long long*)inp_raw;
            a = p[(long long)b * SQ + s];
            c = p[(long long)(BATCH + b) * SQ + s];
        }
        g_pidx[s * BATCH + b] = (int)(a * 4 + c);
    }
    if (i < HB) { g_h1[i] = 0.f; g_h2[i] = 0.f; }   // zero initial states
}

__global__ void setup_e2(const float* __restrict__ embed, const float* __restrict__ Wih) {
    int flat = blockIdx.x * blockDim.x + threadIdx.x;   // 128*256 = 32768 = 16*2048
    int p = flat >> 11, r = flat & 2047;
    const float* e0 = embed + (p >> 2) * H;
    const float* e1 = embed + (p & 3) * H;
    const float* w  = Wih + (size_t)r * H;              // layer 0
    float s = 0.f;
    #pragma unroll 4
    for (int k = 0; k < H; k++) s += (e0[k] + e1[k]) * w[k];
    g_E2[p * 2048 + r] = s;
}

// ---------------- persistent LSTM kernel ----------------
// CTA c owns hidden units [4c, 4c+4): gate rows R = 512*gate + 4c + u.
// Thread roles:
//   GEMM:   ks = warp>>1 (K split /4), bq = (warp&1)*8 + lane&7 (batch quad),
//           rg = lane>>3 (row quad). 16 fp32 accumulators = 4 rows x 4 batches.
//   Update: uu = tid>>6 (unit 0..3), bb = tid&63 (batch). c-state in a register.
__global__ __launch_bounds__(NTHREADS, 1)
void lstm_persist(const float* __restrict__ Wih, const float* __restrict__ Whh,
                  const float* __restrict__ bih, const float* __restrict__ bhh,
                  const float* __restrict__ ln_g, const float* __restrict__ ln_b,
                  const float* __restrict__ Wp,  const float* __restrict__ bp,
                  float* __restrict__ out)
{
    extern __shared__ float sm[];
    float* ws  = sm;                       // [k][16]  weights, up to 1024*16 (64KB)
    float* gp  = ws + 16384;               // [4ks][16r][GPLD] gate partials
    float* E2s = gp + 4 * RPC * GPLD;      // [16p][16r]
    float* bs  = E2s + 256;                // [16r]

    const int cta  = blockIdx.x;
    const int tid  = threadIdx.x;
    const int warp = tid >> 5, lane = tid & 31;
    const int ks = warp >> 1;
    const int bq = ((warp & 1) << 3) + (lane & 7);
    const int rg = lane >> 3;
    const int uu = tid >> 6, bb = tid & 63;
    const int uglob = (cta << 2) + uu;

    // ======== layer 0: load Whh slice (E2 covers the input GEMM) ========
    for (int idx = tid; idx < RPC * H; idx += NTHREADS) {
        int r = idx >> 9, k = idx & (H - 1);
        int R = ((r >> 2) << 9) + (cta << 2) + (r & 3);
        ws[k * RPC + r] = Whh[(size_t)R * H + k];
    }
    for (int idx = tid; idx < 256; idx += NTHREADS) {
        int p = idx >> 4, r = idx & 15;
        int R = ((r >> 2) << 9) + (cta << 2) + (r & 3);
        E2s[idx] = g_E2[p * 2048 + R];
    }
    if (tid < RPC) {
        int R = ((tid >> 2) << 9) + (cta << 2) + (tid & 3);
        bs[tid] = bih[R] + bhh[R];
    }
    __syncthreads();

    float cst = 0.f;
    for (int t = 0; t < SQ; ++t) {
        const float* hsrc = g_h1 + (size_t)t * HB + ks * 128 * BATCH + bq * 4;
        const float* wp2  = ws + ks * 128 * RPC + rg * 4;
        float a[4][4];
        #pragma unroll
        for (int i = 0; i < 4; i++)
            #pragma unroll
            for (int j = 0; j < 4; j++) a[i][j] = 0.f;

        #pragma unroll 4
        for (int kk = 0; kk < 128; ++kk) {
            float4 w4 = *reinterpret_cast<const float4*>(wp2);
            float4 h4 = __ldcg(reinterpret_cast<const float4*>(hsrc));
            float wv[4] = {w4.x, w4.y, w4.z, w4.w};
            float hv[4] = {h4.x, h4.y, h4.z, h4.w};
            #pragma unroll
            for (int i = 0; i < 4; i++)
                #pragma unroll
                for (int j = 0; j < 4; j++) a[i][j] += wv[i] * hv[j];
            wp2  += RPC;
            hsrc += BATCH;
        }
        {
            float* g0 = gp + (ks * RPC + rg * 4) * GPLD + bq * 4;
            #pragma unroll
            for (int i = 0; i < 4; i++)
                *reinterpret_cast<float4*>(g0 + i * GPLD) =
                    make_float4(a[i][0], a[i][1], a[i][2], a[i][3]);
        }
        __syncthreads();

        // elementwise gate update (each thread: one (unit,batch))
        int p = g_pidx[t * BATCH + bb];
        float gv[4];
        #pragma unroll
        for (int gate = 0; gate < 4; ++gate) {
            int r = (gate << 2) + uu;
            float v = bs[r] + E2s[(p << 4) + r];
            v += gp[(0 * RPC + r) * GPLD + bb];
            v += gp[(1 * RPC + r) * GPLD + bb];
            v += gp[(2 * RPC + r) * GPLD + bb];
            v += gp[(3 * RPC + r) * GPLD + bb];
            gv[gate] = v;
        }
        float ig = sigmoidf_(gv[0]);
        float fg = sigmoidf_(gv[1]);
        float gg = tanhf(gv[2]);
        float og = sigmoidf_(gv[3]);
        cst = fg * cst + ig * gg;
        float hv = og * tanhf(cst);
        __stcg(g_h1 + (size_t)(t + 1) * HB + uglob * BATCH + bb, hv);
        grid_barrier();
    }

    // ======== layer 1: K = 1024 (fused input GEMM h1@Wih2^T + h2@Whh2^T) ========
    {
        const float* Wih1 = Wih + (size_t)4 * H * H;
        const float* Whh1 = Whh + (size_t)4 * H * H;
        for (int idx = tid; idx < RPC * 2 * H; idx += NTHREADS) {
            int r = idx >> 10, k = idx & 1023;
            int R = ((r >> 2) << 9) + (cta << 2) + (r & 3);
            float v = (k < H) ? Wih1[(size_t)R * H + k] : Whh1[(size_t)R * H + (k - H)];
            ws[k * RPC + r] = v;
        }
        if (tid < RPC) {
            int R = ((tid >> 2) << 9) + (cta << 2) + (tid & 3);
            bs[tid] = bih[2048 + R] + bhh[2048 + R];
        }
        __syncthreads();
    }

    cst = 0.f;
    for (int t = 0; t < SQ; ++t) {
        const float* xsrc  = g_h1 + (size_t)(t + 1) * HB;   // layer-1 output at step t
        const float* h2src = g_h2 + (size_t)(t & 1) * HB;
        const float* src = (ks < 2) ? (xsrc + ks * 256 * BATCH)
                                    : (h2src + (ks - 2) * 256 * BATCH);
        src += bq * 4;
        const float* wp2 = ws + ks * 256 * RPC + rg * 4;
        float a[4][4];
        #pragma unroll
        for (int i = 0; i < 4; i++)
            #pragma unroll
            for (int j = 0; j < 4; j++) a[i][j] = 0.f;

        #pragma unroll 4
        for (int kk = 0; kk < 256; ++kk) {
            float4 w4 = *reinterpret_cast<const float4*>(wp2);
            float4 h4 = __ldcg(reinterpret_cast<const float4*>(src));
            float wv[4] = {w4.x, w4.y, w4.z, w4.w};
            float hv[4] = {h4.x, h4.y, h4.z, h4.w};
            #pragma unroll
            for (int i = 0; i < 4; i++)
                #pragma unroll
                for (int j = 0; j < 4; j++) a[i][j] += wv[i] * hv[j];
            wp2 += RPC;
            src += BATCH;
        }
        {
            float* g0 = gp + (ks * RPC + rg * 4) * GPLD + bq * 4;
            #pragma unroll
            for (int i = 0; i < 4; i++)
                *reinterpret_cast<float4*>(g0 + i * GPLD) =
                    make_float4(a[i][0], a[i][1], a[i][2], a[i][3]);
        }
        __syncthreads();

        float gv[4];
        #pragma unroll
        for (int gate = 0; gate < 4; ++gate) {
            int r = (gate << 2) + uu;
            float v = bs[r];
            v += gp[(0 * RPC + r) * GPLD + bb];
            v += gp[(1 * RPC + r) * GPLD + bb];
            v += gp[(2 * RPC + r) * GPLD + bb];
            v += gp[(3 * RPC + r) * GPLD + bb];
            gv[gate] = v;
        }
        float ig = sigmoidf_(gv[0]);
        float fg = sigmoidf_(gv[1]);
        float gg = tanhf(gv[2]);
        float og = sigmoidf_(gv[3]);
        cst = fg * cst + ig * gg;
        float hv = og * tanhf(cst);
        __stcg(g_h2 + (size_t)((t + 1) & 1) * HB + uglob * BATCH + bb, hv);
        grid_barrier();
    }

    // ======== head: LayerNorm + projection (final h2 is in slot 0) ========
    if (cta < 8) {
        int b = (cta << 3) + warp;   // 8 CTAs x 8 warps = 64 batches
        const float* h2 = g_h2;
        float s1 = 0.f, s2 = 0.f;
        for (int u = lane; u < H; u += 32) {
            float v = __ldcg(h2 + u * BATCH + b);
            s1 += v; s2 += v * v;
        }
        #pragma unroll
        for (int o = 16; o; o >>= 1) {
            s1 += __shfl_xor_sync(0xFFFFFFFFu, s1, o);
            s2 += __shfl_xor_sync(0xFFFFFFFFu, s2, o);
        }
        float mu  = s1 * (1.f / H);
        float var = s2 * (1.f / H) - mu * mu;
        float rs  = rsqrtf(var + 1e-5f);
        float acc = 0.f;
        for (int u = lane; u < H; u += 32) {
            float v  = __ldcg(h2 + u * BATCH + b);
            float hn = (v - mu) * rs * ln_g[u] + ln_b[u];
            acc += hn * Wp[u];
        }
        #pragma unroll
        for (int o = 16; o; o >>= 1) acc += __shfl_xor_sync(0xFFFFFFFFu, acc, o);
        if (lane == 0) out[b] = acc + bp[0];
    }
}

// ---------------- launch ----------------
extern "C" void kernel_launch(void* const* d_in, const int* in_sizes, int n_in,
                              void* d_out, int out_size) {
    const void*  inp      = d_in[0];
    const float* embed    = (const float*)d_in[1];
    const float* Wih      = (const float*)d_in[2];
    const float* Whh      = (const float*)d_in[3];
    const float* bih      = (const float*)d_in[4];
    const float* bhh      = (const float*)d_in[5];
    const float* ln_g     = (const float*)d_in[6];
    const float* ln_b     = (const float*)d_in[7];
    const float* Wp       = (const float*)d_in[8];
    const float* bp       = (const float*)d_in[9];
    float* out = (float*)d_out;

    detect_reset<<<1, 1>>>();
    detect_dtype<<<512, 256>>>((const unsigned*)inp);
    setup_misc<<<512, 256>>>(inp);
    setup_e2<<<128, 256>>>(embed, Wih);

    int smem = (16384 + 4 * RPC * GPLD + 256 + 16) * 4;   // 84032 bytes
    cudaFuncSetAttribute(lstm_persist, cudaFuncAttributeMaxDynamicSharedMemorySize, smem);
    lstm_persist<<<GRID, NTHREADS, smem>>>(Wih, Whh, bih, bhh, ln_g, ln_b, Wp, bp, out);
}

// round 3
// speedup vs baseline: 1.8917x; 1.8917x over previous
#include <cuda_runtime.h>
#include <cstdint>

// ---------------- problem constants ----------------
#define GRID     128      // CTAs (1 per SM, co-resident -> grid barrier safe)
#define NTHREADS 256
#define SQ       2048
#define BATCH    64
#define H        512
#define HB       (H*BATCH)   // 32768 floats per h snapshot
#define RPC      16          // gate rows per CTA (4 units x 4 gates)
#define GPLD     68          // padded ld for gate-partial smem tile
#define CHUNKF   16384       // staged chunk: K=256 x B=64 floats (64KB)

// ---------------- device scratch ----------------
__device__ __align__(16) float g_h1[(SQ + 1) * HB];
__device__ __align__(16) float g_h2[2 * HB];
__device__ __align__(16) float g_E2[16 * 4 * H];
__device__ int      g_pidx[SQ * BATCH];
__device__ unsigned g_isI32;
__device__ unsigned g_barcnt;
__device__ unsigned g_bargen;

__device__ __forceinline__ float sigmoidf_(float x) { return 1.f / (1.f + expf(-x)); }

// Fence-free grid barrier: release-add arrive, acquire-load poll on monotonic
// generation. target = base_gen_at_kernel_start + local_step (replay-safe).
__device__ __forceinline__ void grid_barrier(unsigned target) {
    __syncthreads();
    if (threadIdx.x == 0) {
        unsigned prev;
        asm volatile("atom.release.gpu.global.add.u32 %0, [%1], %2;"
                     : "=r"(prev) : "l"(&g_barcnt), "r"(1u) : "memory");
        if (prev == GRID - 1u) {
            asm volatile("st.relaxed.gpu.global.u32 [%0], %1;"
                         :: "l"(&g_barcnt), "r"(0u) : "memory");
            asm volatile("st.release.gpu.global.u32 [%0], %1;"
                         :: "l"(&g_bargen), "r"(target) : "memory");
        } else {
            unsigned cur;
            do {
                asm volatile("ld.acquire.gpu.global.u32 %0, [%1];"
                             : "=r"(cur) : "l"(&g_bargen) : "memory");
            } while ((int)(cur - target) < 0);
        }
    }
    __syncthreads();
}

// ---------------- cp.async helpers ----------------
__device__ __forceinline__ void stage_chunk(float* dst, const float* __restrict__ src, int tid) {
    uint32_t s = (uint32_t)__cvta_generic_to_shared(dst) + (uint32_t)tid * 16u;
    const float4* g = reinterpret_cast<const float4*>(src) + tid;
    #pragma unroll
    for (int i = 0; i < 16; i++)
        asm volatile("cp.async.cg.shared.global [%0], [%1], 16;"
                     :: "r"(s + (uint32_t)i * (NTHREADS * 16u)), "l"(g + i * NTHREADS) : "memory");
}
#define CP_COMMIT() asm volatile("cp.async.commit_group;" ::: "memory")
#define CP_WAIT1()  asm volatile("cp.async.wait_group 1;" ::: "memory")
#define CP_WAIT0()  asm volatile("cp.async.wait_group 0;" ::: "memory")

// GEMM over one staged chunk (K=256): thread does 4 rows x 4 batches over 64 k.
__device__ __forceinline__ void gemm_chunk(const float* __restrict__ hc,
                                           const float* __restrict__ wc,
                                           float a[4][4], int ks, int bq, int rg) {
    const float* h = hc + ks * 64 * BATCH + bq * 4;
    const float* w = wc + ks * 64 * RPC + rg * 4;
    #pragma unroll 8
    for (int kk = 0; kk < 64; ++kk) {
        float4 w4 = *reinterpret_cast<const float4*>(w);
        float4 h4 = *reinterpret_cast<const float4*>(h);
        float wv[4] = {w4.x, w4.y, w4.z, w4.w};
        float hv[4] = {h4.x, h4.y, h4.z, h4.w};
        #pragma unroll
        for (int i = 0; i < 4; i++)
            #pragma unroll
            for (int j = 0; j < 4; j++) a[i][j] += wv[i] * hv[j];
        w += RPC; h += BATCH;
    }
}

// ---------------- setup kernels ----------------
__global__ void detect_reset() { g_isI32 = 0u; }

// int64 values in [0,4) -> odd u32 words all zero; int32 -> some nonzero.
__global__ void detect_dtype(const unsigned* __restrict__ w) {
    int i = blockIdx.x * blockDim.x + threadIdx.x;
    if (i < SQ * BATCH) {
        if ((i & 1) && w[i] != 0u) atomicOr(&g_isI32, 1u);
    }
}

__global__ void setup_misc(const void* __restrict__ inp_raw) {
    int i = blockIdx.x * blockDim.x + threadIdx.x;
    if (i < SQ * BATCH) {
        int s = i >> 6, b = i & 63;
        long long a, c;
        if (g_isI32) {
            const int* p = (const int*)inp_raw;
            a = p[b * SQ + s];
            c = p[(BATCH + b) * SQ + s];
        } else {
            const long long* p = (const long long*)inp_raw;
            a = p[(long long)b * SQ + s];
            c = p[(long long)(BATCH + b) * SQ + s];
        }
        g_pidx[s * BATCH + b] = (int)(a * 4 + c);
    }
    if (i < HB) { g_h1[i] = 0.f; g_h2[i] = 0.f; g_h2[HB + i] = 0.f; }
}

__global__ void setup_e2(const float* __restrict__ embed, const float* __restrict__ Wih) {
    int flat = blockIdx.x * blockDim.x + threadIdx.x;
    int p = flat >> 11, r = flat & 2047;
    const float* e0 = embed + (p >> 2) * H;
    const float* e1 = embed + (p & 3) * H;
    const float* w  = Wih + (size_t)r * H;
    float s = 0.f;
    #pragma unroll 4
    for (int k = 0; k < H; k++) s += (e0[k] + e1[k]) * w[k];
    g_E2[p * 2048 + r] = s;
}

// ---------------- persistent LSTM kernel ----------------
__global__ __launch_bounds__(NTHREADS, 1)
void lstm_persist(const float* __restrict__ Wih, const float* __restrict__ Whh,
                  const float* __restrict__ bih, const float* __restrict__ bhh,
                  const float* __restrict__ ln_g, const float* __restrict__ ln_b,
                  const float* __restrict__ Wp,  const float* __restrict__ bp,
                  float* __restrict__ out)
{
    extern __shared__ float sm[];
    float* ws  = sm;                       // 16384 floats  (weights [k][16])
    float* hs  = ws + 16384;               // 32768 floats  (2 x 64KB h chunks)
    float* gp  = hs + 2 * CHUNKF;          // 4*16*GPLD gate partials
    float* E2s = gp + 4 * RPC * GPLD;      // 256
    float* bs  = E2s + 256;                // 16
    __shared__ unsigned s_base;

    const int cta  = blockIdx.x;
    const int tid  = threadIdx.x;
    const int warp = tid >> 5, lane = tid & 31;
    const int ks = warp >> 1;
    const int bq = ((warp & 1) << 3) + (lane & 7);
    const int rg = lane >> 3;
    const int uu = tid >> 6, bb = tid & 63;
    const int uglob = (cta << 2) + uu;

    if (tid == 0) {
        unsigned b_;
        asm volatile("ld.relaxed.gpu.global.u32 %0, [%1];" : "=r"(b_) : "l"(&g_bargen) : "memory");
        s_base = b_;
    }
    __syncthreads();
    unsigned gen = s_base;

    // ======== layer 0 weight/bias/E2 load ========
    for (int idx = tid; idx < RPC * H; idx += NTHREADS) {
        int r = idx >> 9, k = idx & (H - 1);
        int R = ((r >> 2) << 9) + (cta << 2) + (r & 3);
        ws[k * RPC + r] = Whh[(size_t)R * H + k];
    }
    for (int idx = tid; idx < 256; idx += NTHREADS) {
        int p = idx >> 4, r = idx & 15;
        int R = ((r >> 2) << 9) + (cta << 2) + (r & 3);
        E2s[idx] = g_E2[p * 2048 + R];
    }
    if (tid < RPC) {
        int R = ((tid >> 2) << 9) + (cta << 2) + (tid & 3);
        bs[tid] = bih[R] + bhh[R];
    }
    __syncthreads();

    float cst = 0.f;
    for (int t = 0; t < SQ; ++t) {
        const float* hbase = g_h1 + (size_t)t * HB;
        stage_chunk(hs, hbase, tid); CP_COMMIT();
        float a[4][4];
        #pragma unroll
        for (int i = 0; i < 4; i++)
            #pragma unroll
            for (int j = 0; j < 4; j++) a[i][j] = 0.f;

        #pragma unroll
        for (int c = 0; c < 2; ++c) {
            if (c + 1 < 2) { stage_chunk(hs + CHUNKF, hbase + CHUNKF, tid); CP_COMMIT(); CP_WAIT1(); }
            else           { CP_WAIT0(); }
            __syncthreads();
            gemm_chunk(hs + c * CHUNKF, ws + c * 256 * RPC, a, ks, bq, rg);
            if (c + 1 < 2) __syncthreads();
        }
        {
            float* g0 = gp + (ks * RPC + rg * 4) * GPLD + bq * 4;
            #pragma unroll
            for (int i = 0; i < 4; i++)
                *reinterpret_cast<float4*>(g0 + i * GPLD) =
                    make_float4(a[i][0], a[i][1], a[i][2], a[i][3]);
        }
        __syncthreads();

        int p = g_pidx[t * BATCH + bb];
        float gv[4];
        #pragma unroll
        for (int gate = 0; gate < 4; ++gate) {
            int r = (gate << 2) + uu;
            float v = bs[r] + E2s[(p << 4) + r];
            v += gp[(0 * RPC + r) * GPLD + bb];
            v += gp[(1 * RPC + r) * GPLD + bb];
            v += gp[(2 * RPC + r) * GPLD + bb];
            v += gp[(3 * RPC + r) * GPLD + bb];
            gv[gate] = v;
        }
        float ig = sigmoidf_(gv[0]);
        float fg = sigmoidf_(gv[1]);
        float gg = tanhf(gv[2]);
        float og = sigmoidf_(gv[3]);
        cst = fg * cst + ig * gg;
        float hv = og * tanhf(cst);
        __stcg(g_h1 + (size_t)(t + 1) * HB + uglob * BATCH + bb, hv);
        grid_barrier(++gen);
    }

    // ======== layer 1 weights: K=1024 (Wih2 | Whh2) ========
    {
        const float* Wih1 = Wih + (size_t)4 * H * H;
        const float* Whh1 = Whh + (size_t)4 * H * H;
        for (int idx = tid; idx < RPC * 2 * H; idx += NTHREADS) {
            int r = idx >> 10, k = idx & 1023;
            int R = ((r >> 2) << 9) + (cta << 2) + (r & 3);
            float v = (k < H) ? Wih1[(size_t)R * H + k] : Whh1[(size_t)R * H + (k - H)];
            ws[k * RPC + r] = v;
        }
        if (tid < RPC) {
            int R = ((tid >> 2) << 9) + (cta << 2) + (tid & 3);
            bs[tid] = bih[2048 + R] + bhh[2048 + R];
        }
        __syncthreads();
    }

    cst = 0.f;
    for (int t = 0; t < SQ; ++t) {
        const float* xsrc  = g_h1 + (size_t)(t + 1) * HB;
        const float* h2src = g_h2 + (size_t)(t & 1) * HB;
        const float* csrc[4] = { xsrc, xsrc + CHUNKF, h2src, h2src + CHUNKF };

        stage_chunk(hs, csrc[0], tid); CP_COMMIT();
        float a[4][4];
        #pragma unroll
        for (int i = 0; i < 4; i++)
            #pragma unroll
            for (int j = 0; j < 4; j++) a[i][j] = 0.f;

        #pragma unroll
        for (int c = 0; c < 4; ++c) {
            if (c + 1 < 4) { stage_chunk(hs + ((c + 1) & 1) * CHUNKF, csrc[c + 1], tid); CP_COMMIT(); CP_WAIT1(); }
            else           { CP_WAIT0(); }
            __syncthreads();
            gemm_chunk(hs + (c & 1) * CHUNKF, ws + c * 256 * RPC, a, ks, bq, rg);
            if (c + 1 < 4) __syncthreads();
        }
        {
            float* g0 = gp + (ks * RPC + rg * 4) * GPLD + bq * 4;
            #pragma unroll
            for (int i = 0; i < 4; i++)
                *reinterpret_cast<float4*>(g0 + i * GPLD) =
                    make_float4(a[i][0], a[i][1], a[i][2], a[i][3]);
        }
        __syncthreads();

        float gv[4];
        #pragma unroll
        for (int gate = 0; gate < 4; ++gate) {
            int r = (gate << 2) + uu;
            float v = bs[r];
            v += gp[(0 * RPC + r) * GPLD + bb];
            v += gp[(1 * RPC + r) * GPLD + bb];
            v += gp[(2 * RPC + r) * GPLD + bb];
            v += gp[(3 * RPC + r) * GPLD + bb];
            gv[gate] = v;
        }
        float ig = sigmoidf_(gv[0]);
        float fg = sigmoidf_(gv[1]);
        float gg = tanhf(gv[2]);
        float og = sigmoidf_(gv[3]);
        cst = fg * cst + ig * gg;
        float hv = og * tanhf(cst);
        __stcg(g_h2 + (size_t)((t + 1) & 1) * HB + uglob * BATCH + bb, hv);
        grid_barrier(++gen);
    }

    // ======== head: LayerNorm + projection (final h2 in slot 0) ========
    if (cta < 8) {
        int b = (cta << 3) + warp;
        const float* h2 = g_h2;
        float s1 = 0.f, s2 = 0.f;
        for (int u = lane; u < H; u += 32) {
            float v = __ldcg(h2 + u * BATCH + b);
            s1 += v; s2 += v * v;
        }
        #pragma unroll
        for (int o = 16; o; o >>= 1) {
            s1 += __shfl_xor_sync(0xFFFFFFFFu, s1, o);
            s2 += __shfl_xor_sync(0xFFFFFFFFu, s2, o);
        }
        float mu  = s1 * (1.f / H);
        float var = s2 * (1.f / H) - mu * mu;
        float rs  = rsqrtf(var + 1e-5f);
        float acc = 0.f;
        for (int u = lane; u < H; u += 32) {
            float v  = __ldcg(h2 + u * BATCH + b);
            float hn = (v - mu) * rs * ln_g[u] + ln_b[u];
            acc += hn * Wp[u];
        }
        #pragma unroll
        for (int o = 16; o; o >>= 1) acc += __shfl_xor_sync(0xFFFFFFFFu, acc, o);
        if (lane == 0) out[b] = acc + bp[0];
    }
}

// ---------------- launch ----------------
extern "C" void kernel_launch(void* const* d_in, const int* in_sizes, int n_in,
                              void* d_out, int out_size) {
    const void*  inp   = d_in[0];
    const float* embed = (const float*)d_in[1];
    const float* Wih   = (const float*)d_in[2];
    const float* Whh   = (const float*)d_in[3];
    const float* bih   = (const float*)d_in[4];
    const float* bhh   = (const float*)d_in[5];
    const float* ln_g  = (const float*)d_in[6];
    const float* ln_b  = (const float*)d_in[7];
    const float* Wp    = (const float*)d_in[8];
    const float* bp    = (const float*)d_in[9];
    float* out = (float*)d_out;

    detect_reset<<<1, 1>>>();
    detect_dtype<<<512, 256>>>((const unsigned*)inp);
    setup_misc<<<512, 256>>>(inp);
    setup_e2<<<128, 256>>>(embed, Wih);

    int smem = (16384 + 2 * CHUNKF + 4 * RPC * GPLD + 256 + 16) * 4;  // 215,104 B
    cudaFuncSetAttribute(lstm_persist, cudaFuncAttributeMaxDynamicSharedMemorySize, smem);
    lstm_persist<<<GRID, NTHREADS, smem>>>(Wih, Whh, bih, bhh, ln_g, ln_b, Wp, bp, out);
}